// round 15
// baseline (speedup 1.0000x reference)
#include <cuda_runtime.h>
#include <cuda_fp16.h>
#include <cstdint>

// GraphConv: out = relu( segment_sum(feature[src] -> dst) @ W^T + b )
// R15: 2-launch pipeline.
//   1) fused: [blocks 0..390]  gemm h16 = fp16(feature @ W^T), W-fragment
//                              table built per-block in smem (no prep dep)
//             [blocks 391.. ]  fill capacity-binned CSR (cursors are
//                              zero-init'd / self-cleaned by gather)
//   2) gather: warp-per-node over h16, + bias, relu, out; resets cursor;
//              deg>CAP fallback = exact edge-list rescan (no overflow state).

constexpr int N_NODES = 50000;
constexpr int N_EDGES = 800000;
constexpr int D       = 128;
constexpr int CAP     = 128;

constexpr int GEMM_WARPS  = N_NODES / 16;                 // 3125
constexpr int GEMM_BLOCKS = (GEMM_WARPS + 7) / 8;         // 391 (256 thr = 8 warps)
constexpr int FILL_BLOCKS = (N_EDGES / 4 + 255) / 256;    // 782

// ---- static scratch (zero-initialized at module load) ----
__device__ __half g_h16[N_NODES * D];        // 12.8 MB h = fp16(feature @ W^T)
__device__ int    g_bins[N_NODES * CAP];     // 25.6 MB binned src ids
__device__ int    g_cursor[N_NODES];         // in-degree counter (self-cleaning)

// ---------------------------------------------------------------------------
// helpers
// ---------------------------------------------------------------------------
__device__ __forceinline__ uint32_t pack_h2(float a, float b) {
    __half2 h = __floats2half2_rn(a, b);
    return *reinterpret_cast<uint32_t*>(&h);
}

__device__ __forceinline__ void mma_f16(
    float& d0, float& d1, float& d2, float& d3,
    uint32_t a0, uint32_t a1, uint32_t a2, uint32_t a3,
    uint32_t b0, uint32_t b1)
{
    asm volatile(
        "mma.sync.aligned.m16n8k16.row.col.f32.f16.f16.f32 "
        "{%0,%1,%2,%3}, {%4,%5,%6,%7}, {%8,%9}, {%0,%1,%2,%3};"
        : "+f"(d0), "+f"(d1), "+f"(d2), "+f"(d3)
        : "r"(a0), "r"(a1), "r"(a2), "r"(a3), "r"(b0), "r"(b1));
}

// ---------------------------------------------------------------------------
// 1) fused gemm + fill
// ---------------------------------------------------------------------------
__device__ void gemm_warp_body(int gw, int lane, const float* __restrict__ feat,
                               const uint4* __restrict__ wfrag)
{
    int gp = lane >> 2;
    int tg = lane & 3;
    int r0 = gw * 16 + gp;                                   // rows r0, r0+8

    float acc[16][4];
#pragma unroll
    for (int nt = 0; nt < 16; nt++)
#pragma unroll
        for (int j = 0; j < 4; j++) acc[nt][j] = 0.f;

#pragma unroll
    for (int ks = 0; ks < 8; ks++) {
        int k0 = 16 * ks + 2 * tg;
        float2 f0 = *reinterpret_cast<const float2*>(feat + (r0    ) * D + k0    );
        float2 f1 = *reinterpret_cast<const float2*>(feat + (r0 + 8) * D + k0    );
        float2 f2 = *reinterpret_cast<const float2*>(feat + (r0    ) * D + k0 + 8);
        float2 f3 = *reinterpret_cast<const float2*>(feat + (r0 + 8) * D + k0 + 8);
        uint32_t a0 = pack_h2(f0.x, f0.y);
        uint32_t a1 = pack_h2(f1.x, f1.y);
        uint32_t a2 = pack_h2(f2.x, f2.y);
        uint32_t a3 = pack_h2(f3.x, f3.y);
#pragma unroll
        for (int np = 0; np < 8; np++) {
            uint4 b = wfrag[ks * 256 + np * 32 + lane];      // LDS.128, conflict-free
            mma_f16(acc[2 * np][0], acc[2 * np][1], acc[2 * np][2], acc[2 * np][3],
                    a0, a1, a2, a3, b.x, b.y);
            mma_f16(acc[2 * np + 1][0], acc[2 * np + 1][1],
                    acc[2 * np + 1][2], acc[2 * np + 1][3],
                    a0, a1, a2, a3, b.z, b.w);
        }
    }

#pragma unroll
    for (int nt = 0; nt < 16; nt++) {
        int c = nt * 8 + 2 * tg;
        *reinterpret_cast<uint32_t*>(g_h16 + (r0    ) * D + c) =
            pack_h2(acc[nt][0], acc[nt][1]);
        *reinterpret_cast<uint32_t*>(g_h16 + (r0 + 8) * D + c) =
            pack_h2(acc[nt][2], acc[nt][3]);
    }
}

__global__ void __launch_bounds__(256) fused_gemm_fill_kernel(
    const float* __restrict__ feat, const float* __restrict__ Wm,
    const int* __restrict__ ei)
{
    __shared__ uint4 wfrag[8 * 8 * 32];      // 32 KB W fragment table

    if (blockIdx.x < GEMM_BLOCKS) {
        // build fragment-major fp16 W table in smem (mapping validated R9-R14)
        for (int i = threadIdx.x; i < 2048; i += 256) {
            int ks   = i >> 8;
            int np   = (i >> 5) & 7;
            int lane = i & 31;
            int gp   = lane >> 2;
            int tg   = lane & 3;
            int k0   = 16 * ks + 2 * tg;
            int n0   = 16 * np + gp;
            uint4 v;
            v.x = pack_h2(Wm[n0 * D + k0    ], Wm[n0 * D + k0 + 1]);
            v.y = pack_h2(Wm[n0 * D + k0 + 8], Wm[n0 * D + k0 + 9]);
            v.z = pack_h2(Wm[(n0 + 8) * D + k0    ], Wm[(n0 + 8) * D + k0 + 1]);
            v.w = pack_h2(Wm[(n0 + 8) * D + k0 + 8], Wm[(n0 + 8) * D + k0 + 9]);
            wfrag[i] = v;
        }
        __syncthreads();

        int gw = blockIdx.x * 8 + (threadIdx.x >> 5);
        if (gw < GEMM_WARPS)
            gemm_warp_body(gw, threadIdx.x & 31, feat, wfrag);
    } else {
        int i = (blockIdx.x - GEMM_BLOCKS) * 256 + threadIdx.x;
        if (i < N_EDGES / 4) {
            int4 s = reinterpret_cast<const int4*>(ei)[i];
            int4 d = reinterpret_cast<const int4*>(ei + N_EDGES)[i];
            int p0 = atomicAdd(&g_cursor[d.x], 1);
            int p1 = atomicAdd(&g_cursor[d.y], 1);
            int p2 = atomicAdd(&g_cursor[d.z], 1);
            int p3 = atomicAdd(&g_cursor[d.w], 1);
            if (p0 < CAP) g_bins[d.x * CAP + p0] = s.x;
            if (p1 < CAP) g_bins[d.y * CAP + p1] = s.y;
            if (p2 < CAP) g_bins[d.z * CAP + p2] = s.z;
            if (p3 < CAP) g_bins[d.w * CAP + p3] = s.w;
        }
    }
}

// ---------------------------------------------------------------------------
// 2) gather: warp-per-node, int4 bin loads, fp32 adds, + bias, relu, store.
//    Self-cleans g_cursor.  deg>CAP (expected never): exact rescan of ei.
// ---------------------------------------------------------------------------
__device__ __forceinline__ void acc_add(float4& a, uint2 u) {
    __half2 h0 = *reinterpret_cast<__half2*>(&u.x);
    __half2 h1 = *reinterpret_cast<__half2*>(&u.y);
    float2 f0 = __half22float2(h0);
    float2 f1 = __half22float2(h1);
    a.x += f0.x; a.y += f0.y; a.z += f1.x; a.w += f1.y;
}

__global__ void __launch_bounds__(256) gather_kernel(
    const int* __restrict__ ei, const float* __restrict__ bias,
    float* __restrict__ out)
{
    int warp = (blockIdx.x * blockDim.x + threadIdx.x) >> 5;
    int lane = threadIdx.x & 31;
    if (warp >= N_NODES) return;

    const uint2* f = reinterpret_cast<const uint2*>(g_h16);   // 32 uint2/row

    int degf = g_cursor[warp];
    if (lane == 0) g_cursor[warp] = 0;       // self-clean for next graph replay

    float4 acc = make_float4(0.f, 0.f, 0.f, 0.f);

    if (degf <= CAP) {
        const int4* bin4 = reinterpret_cast<const int4*>(&g_bins[warp * CAP]);
        int ng = degf >> 2;
        int g  = 0;
        for (; g + 2 <= ng; g += 2) {        // 8 edges in flight
            int4 sa = bin4[g];
            int4 sb = bin4[g + 1];
            uint2 u0 = f[sa.x * 32 + lane];
            uint2 u1 = f[sa.y * 32 + lane];
            uint2 u2 = f[sa.z * 32 + lane];
            uint2 u3 = f[sa.w * 32 + lane];
            uint2 u4 = f[sb.x * 32 + lane];
            uint2 u5 = f[sb.y * 32 + lane];
            uint2 u6 = f[sb.z * 32 + lane];
            uint2 u7 = f[sb.w * 32 + lane];
            acc_add(acc, u0); acc_add(acc, u1);
            acc_add(acc, u2); acc_add(acc, u3);
            acc_add(acc, u4); acc_add(acc, u5);
            acc_add(acc, u6); acc_add(acc, u7);
        }
        for (; g < ng; g++) {
            int4 s = bin4[g];
            uint2 u0 = f[s.x * 32 + lane];
            uint2 u1 = f[s.y * 32 + lane];
            uint2 u2 = f[s.z * 32 + lane];
            uint2 u3 = f[s.w * 32 + lane];
            acc_add(acc, u0); acc_add(acc, u1);
            acc_add(acc, u2); acc_add(acc, u3);
        }
        for (int e = ng * 4; e < degf; e++) {
            uint2 u = f[g_bins[warp * CAP + e] * 32 + lane];
            acc_add(acc, u);
        }
    } else {
        // exact fallback: rescan the whole edge list for this node
        for (int j = 0; j < N_EDGES; j++) {
            if (__ldg(&ei[N_EDGES + j]) == warp) {
                uint2 u = f[__ldg(&ei[j]) * 32 + lane];
                acc_add(acc, u);
            }
        }
    }

    float4 bv = *reinterpret_cast<const float4*>(bias + lane * 4);
    float4 r;
    r.x = fmaxf(acc.x + bv.x, 0.f);
    r.y = fmaxf(acc.y + bv.y, 0.f);
    r.z = fmaxf(acc.z + bv.z, 0.f);
    r.w = fmaxf(acc.w + bv.w, 0.f);
    reinterpret_cast<float4*>(out)[warp * 32 + lane] = r;
}

// ---------------------------------------------------------------------------
extern "C" void kernel_launch(void* const* d_in, const int* in_sizes, int n_in,
                              void* d_out, int out_size)
{
    const float* feature = (const float*)d_in[0];   // [50000,128]
    const float* Wm      = (const float*)d_in[1];   // [128,128]
    const float* bias    = (const float*)d_in[2];   // [128]
    const int*   ei      = (const int*)  d_in[3];   // [2,800000]
    float*       out     = (float*)d_out;           // [50000,128]

    (void)in_sizes; (void)n_in; (void)out_size;

    fused_gemm_fill_kernel<<<GEMM_BLOCKS + FILL_BLOCKS, 256>>>(feature, Wm, ei);
    {
        int total_threads = N_NODES * 32;
        gather_kernel<<<(total_threads + 255) / 256, 256>>>(ei, bias, out);
    }
}

// round 16
// speedup vs baseline: 1.1519x; 1.1519x over previous
#include <cuda_runtime.h>
#include <cuda_fp16.h>
#include <cstdint>

// GraphConv: out = relu( segment_sum(feature[src] -> dst) @ W^T + b )
// R16: 2-launch pipeline, gather restored to R14 code shape.
//   1) fused: [blocks 0..390]  gemm h16 = fp16(feature @ W^T) (smem W table)
//             [blocks 391.. ]  fill capacity-binned CSR
//   2) gather: warp-per-node (R14 shape), + bias, relu, out; self-cleans
//      cursor; deg>CAP guard calls __noinline__ exact rescan (expected never).

constexpr int N_NODES = 50000;
constexpr int N_EDGES = 800000;
constexpr int D       = 128;
constexpr int CAP     = 128;

constexpr int GEMM_WARPS  = N_NODES / 16;                 // 3125
constexpr int GEMM_BLOCKS = (GEMM_WARPS + 7) / 8;         // 391 (256 thr = 8 warps)
constexpr int FILL_BLOCKS = (N_EDGES / 4 + 255) / 256;    // 782

// ---- static scratch (zero-initialized at module load) ----
__device__ __half g_h16[N_NODES * D];        // 12.8 MB h = fp16(feature @ W^T)
__device__ int    g_bins[N_NODES * CAP];     // 25.6 MB binned src ids
__device__ int    g_cursor[N_NODES];         // in-degree counter (self-cleaning)

// ---------------------------------------------------------------------------
// helpers
// ---------------------------------------------------------------------------
__device__ __forceinline__ uint32_t pack_h2(float a, float b) {
    __half2 h = __floats2half2_rn(a, b);
    return *reinterpret_cast<uint32_t*>(&h);
}

__device__ __forceinline__ void mma_f16(
    float& d0, float& d1, float& d2, float& d3,
    uint32_t a0, uint32_t a1, uint32_t a2, uint32_t a3,
    uint32_t b0, uint32_t b1)
{
    asm volatile(
        "mma.sync.aligned.m16n8k16.row.col.f32.f16.f16.f32 "
        "{%0,%1,%2,%3}, {%4,%5,%6,%7}, {%8,%9}, {%0,%1,%2,%3};"
        : "+f"(d0), "+f"(d1), "+f"(d2), "+f"(d3)
        : "r"(a0), "r"(a1), "r"(a2), "r"(a3), "r"(b0), "r"(b1));
}

// ---------------------------------------------------------------------------
// 1) fused gemm + fill
// ---------------------------------------------------------------------------
__device__ void gemm_warp_body(int gw, int lane, const float* __restrict__ feat,
                               const uint4* __restrict__ wfrag)
{
    int gp = lane >> 2;
    int tg = lane & 3;
    int r0 = gw * 16 + gp;                                   // rows r0, r0+8

    float acc[16][4];
#pragma unroll
    for (int nt = 0; nt < 16; nt++)
#pragma unroll
        for (int j = 0; j < 4; j++) acc[nt][j] = 0.f;

#pragma unroll
    for (int ks = 0; ks < 8; ks++) {
        int k0 = 16 * ks + 2 * tg;
        float2 f0 = *reinterpret_cast<const float2*>(feat + (r0    ) * D + k0    );
        float2 f1 = *reinterpret_cast<const float2*>(feat + (r0 + 8) * D + k0    );
        float2 f2 = *reinterpret_cast<const float2*>(feat + (r0    ) * D + k0 + 8);
        float2 f3 = *reinterpret_cast<const float2*>(feat + (r0 + 8) * D + k0 + 8);
        uint32_t a0 = pack_h2(f0.x, f0.y);
        uint32_t a1 = pack_h2(f1.x, f1.y);
        uint32_t a2 = pack_h2(f2.x, f2.y);
        uint32_t a3 = pack_h2(f3.x, f3.y);
#pragma unroll
        for (int np = 0; np < 8; np++) {
            uint4 b = wfrag[ks * 256 + np * 32 + lane];      // LDS.128, conflict-free
            mma_f16(acc[2 * np][0], acc[2 * np][1], acc[2 * np][2], acc[2 * np][3],
                    a0, a1, a2, a3, b.x, b.y);
            mma_f16(acc[2 * np + 1][0], acc[2 * np + 1][1],
                    acc[2 * np + 1][2], acc[2 * np + 1][3],
                    a0, a1, a2, a3, b.z, b.w);
        }
    }

#pragma unroll
    for (int nt = 0; nt < 16; nt++) {
        int c = nt * 8 + 2 * tg;
        *reinterpret_cast<uint32_t*>(g_h16 + (r0    ) * D + c) =
            pack_h2(acc[nt][0], acc[nt][1]);
        *reinterpret_cast<uint32_t*>(g_h16 + (r0 + 8) * D + c) =
            pack_h2(acc[nt][2], acc[nt][3]);
    }
}

__global__ void __launch_bounds__(256) fused_gemm_fill_kernel(
    const float* __restrict__ feat, const float* __restrict__ Wm,
    const int* __restrict__ ei)
{
    __shared__ uint4 wfrag[8 * 8 * 32];      // 32 KB W fragment table

    if (blockIdx.x < GEMM_BLOCKS) {
        // build fragment-major fp16 W table in smem (mapping validated R9-R14)
        for (int i = threadIdx.x; i < 2048; i += 256) {
            int ks   = i >> 8;
            int np   = (i >> 5) & 7;
            int lane = i & 31;
            int gp   = lane >> 2;
            int tg   = lane & 3;
            int k0   = 16 * ks + 2 * tg;
            int n0   = 16 * np + gp;
            uint4 v;
            v.x = pack_h2(Wm[n0 * D + k0    ], Wm[n0 * D + k0 + 1]);
            v.y = pack_h2(Wm[n0 * D + k0 + 8], Wm[n0 * D + k0 + 9]);
            v.z = pack_h2(Wm[(n0 + 8) * D + k0    ], Wm[(n0 + 8) * D + k0 + 1]);
            v.w = pack_h2(Wm[(n0 + 8) * D + k0 + 8], Wm[(n0 + 8) * D + k0 + 9]);
            wfrag[i] = v;
        }
        __syncthreads();

        int gw = blockIdx.x * 8 + (threadIdx.x >> 5);
        if (gw < GEMM_WARPS)
            gemm_warp_body(gw, threadIdx.x & 31, feat, wfrag);
    } else {
        int i = (blockIdx.x - GEMM_BLOCKS) * 256 + threadIdx.x;
        if (i < N_EDGES / 4) {
            int4 s = reinterpret_cast<const int4*>(ei)[i];
            int4 d = reinterpret_cast<const int4*>(ei + N_EDGES)[i];
            int p0 = atomicAdd(&g_cursor[d.x], 1);
            int p1 = atomicAdd(&g_cursor[d.y], 1);
            int p2 = atomicAdd(&g_cursor[d.z], 1);
            int p3 = atomicAdd(&g_cursor[d.w], 1);
            if (p0 < CAP) g_bins[d.x * CAP + p0] = s.x;
            if (p1 < CAP) g_bins[d.y * CAP + p1] = s.y;
            if (p2 < CAP) g_bins[d.z * CAP + p2] = s.z;
            if (p3 < CAP) g_bins[d.w * CAP + p3] = s.w;
        }
    }
}

// ---------------------------------------------------------------------------
// 2) gather: warp-per-node, R14 code shape.  Self-cleans cursor.
// ---------------------------------------------------------------------------
__device__ __forceinline__ void acc_add(float4& a, uint2 u) {
    __half2 h0 = *reinterpret_cast<__half2*>(&u.x);
    __half2 h1 = *reinterpret_cast<__half2*>(&u.y);
    float2 f0 = __half22float2(h0);
    float2 f1 = __half22float2(h1);
    a.x += f0.x; a.y += f0.y; a.z += f1.x; a.w += f1.y;
}

// exact fallback for deg>CAP nodes (expected never; isolated from fast path)
__device__ __noinline__ void rescan_node(
    int node, int lane, const int* __restrict__ ei, float4* accp)
{
    const uint2* f = reinterpret_cast<const uint2*>(g_h16);
    float4 acc = make_float4(0.f, 0.f, 0.f, 0.f);
    for (int j = 0; j < N_EDGES; j++) {
        if (__ldg(&ei[N_EDGES + j]) == node) {
            uint2 u = f[__ldg(&ei[j]) * 32 + lane];
            acc_add(acc, u);
        }
    }
    *accp = acc;
}

__global__ void __launch_bounds__(256) gather_kernel(
    const int* __restrict__ ei, const float* __restrict__ bias,
    float* __restrict__ out)
{
    int warp = (blockIdx.x * blockDim.x + threadIdx.x) >> 5;
    int lane = threadIdx.x & 31;
    if (warp >= N_NODES) return;

    const uint2* f = reinterpret_cast<const uint2*>(g_h16);   // 32 uint2/row

    int degf = g_cursor[warp];
    if (lane == 0) g_cursor[warp] = 0;       // self-clean for next graph replay
    int deg = (degf <= CAP) ? degf : 0;      // overflow nodes skip fast path

    const int4* bin4 = reinterpret_cast<const int4*>(&g_bins[warp * CAP]);

    float4 acc = make_float4(0.f, 0.f, 0.f, 0.f);

    int ng = deg >> 2;
    int g  = 0;
    for (; g + 2 <= ng; g += 2) {            // 8 edges in flight
        int4 sa = bin4[g];
        int4 sb = bin4[g + 1];
        uint2 u0 = f[sa.x * 32 + lane];
        uint2 u1 = f[sa.y * 32 + lane];
        uint2 u2 = f[sa.z * 32 + lane];
        uint2 u3 = f[sa.w * 32 + lane];
        uint2 u4 = f[sb.x * 32 + lane];
        uint2 u5 = f[sb.y * 32 + lane];
        uint2 u6 = f[sb.z * 32 + lane];
        uint2 u7 = f[sb.w * 32 + lane];
        acc_add(acc, u0); acc_add(acc, u1);
        acc_add(acc, u2); acc_add(acc, u3);
        acc_add(acc, u4); acc_add(acc, u5);
        acc_add(acc, u6); acc_add(acc, u7);
    }
    for (; g < ng; g++) {
        int4 s = bin4[g];
        uint2 u0 = f[s.x * 32 + lane];
        uint2 u1 = f[s.y * 32 + lane];
        uint2 u2 = f[s.z * 32 + lane];
        uint2 u3 = f[s.w * 32 + lane];
        acc_add(acc, u0); acc_add(acc, u1);
        acc_add(acc, u2); acc_add(acc, u3);
    }
    for (int e = ng * 4; e < deg; e++) {
        uint2 u = f[g_bins[warp * CAP + e] * 32 + lane];
        acc_add(acc, u);
    }

    if (degf > CAP)                          // expected never; exact rescan
        rescan_node(warp, lane, ei, &acc);

    float4 bv = *reinterpret_cast<const float4*>(bias + lane * 4);
    float4 r;
    r.x = fmaxf(acc.x + bv.x, 0.f);
    r.y = fmaxf(acc.y + bv.y, 0.f);
    r.z = fmaxf(acc.z + bv.z, 0.f);
    r.w = fmaxf(acc.w + bv.w, 0.f);
    reinterpret_cast<float4*>(out)[warp * 32 + lane] = r;
}

// ---------------------------------------------------------------------------
extern "C" void kernel_launch(void* const* d_in, const int* in_sizes, int n_in,
                              void* d_out, int out_size)
{
    const float* feature = (const float*)d_in[0];   // [50000,128]
    const float* Wm      = (const float*)d_in[1];   // [128,128]
    const float* bias    = (const float*)d_in[2];   // [128]
    const int*   ei      = (const int*)  d_in[3];   // [2,800000]
    float*       out     = (float*)d_out;           // [50000,128]

    (void)in_sizes; (void)n_in; (void)out_size;

    fused_gemm_fill_kernel<<<GEMM_BLOCKS + FILL_BLOCKS, 256>>>(feature, Wm, ei);
    {
        int total_threads = N_NODES * 32;
        gather_kernel<<<(total_threads + 255) / 256, 256>>>(ei, bias, out);
    }
}